// round 13
// baseline (speedup 1.0000x reference)
#include <cuda_runtime.h>
#include <math.h>

#define BATCH 4
#define SEQ   2048
#define DIM   512
#define HEADS 8
#define DK    64
#define ROWS  (BATCH*SEQ)   // 8192

// ---------------- scratch (static device arrays; no allocation) ----------------
__device__ float g_xn[ROWS*DIM];
__device__ float g_q [ROWS*DIM];
__device__ float g_k [ROWS*DIM];
__device__ float g_v [ROWS*DIM];
__device__ float g_ao[ROWS*DIM];
__device__ float g_wr[4*DIM*DIM];   // tf32-rounded weights: Wq,Wk,Wv,Wo

// ---------------- helpers ----------------
__device__ __forceinline__ unsigned f2tf(float x) {
    unsigned r; asm("cvt.rna.tf32.f32 %0, %1;" : "=r"(r) : "f"(x)); return r;
}
__device__ __forceinline__ float f2tff(float x) {
    return __uint_as_float(f2tf(x));
}
__device__ __forceinline__ void mma8(float* c, const unsigned* a, const unsigned* b) {
    asm volatile("mma.sync.aligned.m16n8k8.row.col.f32.tf32.tf32.f32 "
        "{%0,%1,%2,%3}, {%4,%5,%6,%7}, {%8,%9}, {%0,%1,%2,%3};"
        : "+f"(c[0]), "+f"(c[1]), "+f"(c[2]), "+f"(c[3])
        : "r"(a[0]), "r"(a[1]), "r"(a[2]), "r"(a[3]), "r"(b[0]), "r"(b[1]));
}
__device__ __forceinline__ unsigned sptr(const void* p) {
    return (unsigned)__cvta_generic_to_shared(p);
}
__device__ __forceinline__ void cpa16(unsigned dst, const float* src) {
    asm volatile("cp.async.cg.shared.global [%0], [%1], 16;" :: "r"(dst), "l"(src));
}
__device__ __forceinline__ void cpa_commit() { asm volatile("cp.async.commit_group;"); }
template<int N> __device__ __forceinline__ void cpa_wait() {
    asm volatile("cp.async.wait_group %0;" :: "n"(N));
}

// ---------------- LayerNorm: one block per row (output tf32-rounded) ----------------
__global__ void ln_kernel(const float* __restrict__ x,
                          const float* __restrict__ gamma,
                          const float* __restrict__ beta,
                          float* __restrict__ out) {
    int row = blockIdx.x;
    const float* xr = x + (size_t)row * DIM;
    int t = threadIdx.x;
    float vals[4];
    float s = 0.f, ss = 0.f;
#pragma unroll
    for (int i = 0; i < 4; i++) {
        float v = xr[t + i * 128];
        vals[i] = v; s += v; ss += v * v;
    }
#pragma unroll
    for (int off = 16; off; off >>= 1) {
        s  += __shfl_xor_sync(0xffffffffu, s,  off);
        ss += __shfl_xor_sync(0xffffffffu, ss, off);
    }
    __shared__ float red0[4], red1[4];
    int w = t >> 5;
    if ((t & 31) == 0) { red0[w] = s; red1[w] = ss; }
    __syncthreads();
    s  = red0[0] + red0[1] + red0[2] + red0[3];
    ss = red1[0] + red1[1] + red1[2] + red1[3];
    float mu   = s * (1.0f / DIM);
    float var  = ss * (1.0f / DIM) - mu * mu;
    float rstd = rsqrtf(var + 1e-5f);
    float* outr = out + (size_t)row * DIM;
#pragma unroll
    for (int i = 0; i < 4; i++) {
        int c = t + i * 128;
        outr[c] = f2tff((vals[i] - mu) * rstd * gamma[c] + beta[c]);
    }
}

// ---------------- weight pre-rounding (once per replay, 4MB) ----------------
__global__ void round_w_kernel(const float* __restrict__ Wq, const float* __restrict__ Wk,
                               const float* __restrict__ Wv, const float* __restrict__ Wo,
                               float* __restrict__ out) {
    const float* src = (blockIdx.y == 0) ? Wq : (blockIdx.y == 1) ? Wk
                     : (blockIdx.y == 2) ? Wv : Wo;
    int i = (blockIdx.x * 256 + threadIdx.x) * 4;
    float4 v = *(const float4*)(src + i);
    float4 o;
    o.x = f2tff(v.x); o.y = f2tff(v.y); o.z = f2tff(v.z); o.w = f2tff(v.w);
    *(float4*)(out + (size_t)blockIdx.y * DIM * DIM + i) = o;
}

// ---------------- TF32 tensor-core GEMM (cp.async double-buffered) ----------------
// Y[M,512] = (A[M,512] @ W[512,512]^T + bias) * out_scale. A and W pre-rounded.
// Block tile 128x128, BK=16, 128 threads (4 warps as 2m x 2n, warp tile 64x64).
#define GSTR 20

__device__ __forceinline__ void gemm_issue(unsigned* As, unsigned* Bs,
                                           const float* Abase, const float* Wbase,
                                           int k0, int tid) {
#pragma unroll
    for (int p = 0; p < 4; p++) {
        int idx = tid + p * 128;
        int r = idx >> 2, cc = (idx & 3) * 4;
        cpa16(sptr(&As[r * GSTR + cc]), Abase + (size_t)r * 512 + k0 + cc);
        cpa16(sptr(&Bs[r * GSTR + cc]), Wbase + (size_t)r * 512 + k0 + cc);
    }
}

__device__ __forceinline__ void gemm_tf32_body(const float* __restrict__ A,
                                               const float* __restrict__ W,
                                               const float* __restrict__ bias,
                                               float* __restrict__ Y,
                                               unsigned* sm, bool round_out,
                                               float out_scale) {
    unsigned* AsB[2] = {sm,              sm + 128 * GSTR};
    unsigned* BsB[2] = {sm + 2*128*GSTR, sm + 3*128*GSTR};
    int tid = threadIdx.x;
    int lane = tid & 31, wid = tid >> 5;
    int g = lane >> 2, t4 = lane & 3;
    int wm = (wid & 1) * 64;
    int wn = (wid >> 1) * 64;
    int m0 = blockIdx.y * 128, n0 = blockIdx.x * 128;

    float c[4][8][4] = {};

    const float* Abase = A + (size_t)m0 * 512;
    const float* Wbase = W + (size_t)n0 * 512;

    gemm_issue(AsB[0], BsB[0], Abase, Wbase, 0, tid);  cpa_commit();
    gemm_issue(AsB[1], BsB[1], Abase, Wbase, 16, tid); cpa_commit();

    int buf = 0;
    for (int it = 0; it < 32; it++) {
        if (it == 31) cpa_wait<0>(); else cpa_wait<1>();
        __syncthreads();
        unsigned* As = AsB[buf];
        unsigned* Bs = BsB[buf];
#pragma unroll
        for (int ks = 0; ks < 16; ks += 8) {
            unsigned a[4][4], b[8][2];
#pragma unroll
            for (int mi = 0; mi < 4; mi++) {
                int base = (wm + mi * 16 + g) * GSTR + ks + t4;
                a[mi][0] = As[base];
                a[mi][1] = As[base + 8 * GSTR];
                a[mi][2] = As[base + 4];
                a[mi][3] = As[base + 8 * GSTR + 4];
            }
#pragma unroll
            for (int ni = 0; ni < 8; ni++) {
                int bb = (wn + ni * 8 + g) * GSTR + ks + t4;
                b[ni][0] = Bs[bb];
                b[ni][1] = Bs[bb + 4];
            }
#pragma unroll
            for (int mi = 0; mi < 4; mi++)
#pragma unroll
                for (int ni = 0; ni < 8; ni++)
                    mma8(c[mi][ni], a[mi], b[ni]);
        }
        __syncthreads();
        if (it < 30) {
            gemm_issue(As, Bs, Abase, Wbase, (it + 2) * 16, tid);
            cpa_commit();
        }
        buf ^= 1;
    }

#pragma unroll
    for (int mi = 0; mi < 4; mi++) {
        int row = m0 + wm + mi * 16 + g;
#pragma unroll
        for (int ni = 0; ni < 8; ni++) {
            int col = n0 + wn + ni * 8 + 2 * t4;
            float2 bv = *(const float2*)(bias + col);
            float2 o0, o1;
            if (round_out) {
                o0.x = f2tff((c[mi][ni][0] + bv.x) * out_scale);
                o0.y = f2tff((c[mi][ni][1] + bv.y) * out_scale);
                o1.x = f2tff((c[mi][ni][2] + bv.x) * out_scale);
                o1.y = f2tff((c[mi][ni][3] + bv.y) * out_scale);
            } else {
                o0.x = c[mi][ni][0] + bv.x; o0.y = c[mi][ni][1] + bv.y;
                o1.x = c[mi][ni][2] + bv.x; o1.y = c[mi][ni][3] + bv.y;
            }
            *(float2*)(Y + (size_t)row * 512 + col) = o0;
            *(float2*)(Y + (size_t)(row + 8) * 512 + col) = o1;
        }
    }
}

#define GEMM_SMEM (4 * 128 * GSTR * (int)sizeof(unsigned))   // 40960 B

// QKV: one launch, gridDim.z = 3. Q output pre-scaled by DK^-0.5 (exact pow2).
__global__ __launch_bounds__(128) void gemm_qkv_kernel(const float* __restrict__ A,
                                                       const float* __restrict__ Wr,
                                                       const float* __restrict__ bq,
                                                       float* __restrict__ Yq,
                                                       const float* __restrict__ bk,
                                                       float* __restrict__ Yk,
                                                       const float* __restrict__ bv,
                                                       float* __restrict__ Yv) {
    extern __shared__ unsigned gsm[];
    const float* bias; float* Y; float scl;
    if (blockIdx.z == 0)      { bias = bq; Y = Yq; scl = 0.125f; }
    else if (blockIdx.z == 1) { bias = bk; Y = Yk; scl = 1.0f; }
    else                      { bias = bv; Y = Yv; scl = 1.0f; }
    const float* W = Wr + (size_t)blockIdx.z * DIM * DIM;
    gemm_tf32_body(A, W, bias, Y, gsm, true, scl);
}

__global__ __launch_bounds__(128) void gemm_tf32_kernel(const float* __restrict__ A,
                                                        const float* __restrict__ W,
                                                        const float* __restrict__ bias,
                                                        float* __restrict__ Y) {
    extern __shared__ unsigned gsm[];
    gemm_tf32_body(A, W, bias, Y, gsm, false, 1.0f);
}

// ---------------- TF32 tensor-core flash attention ----------------
// Block: 256 thr (8 warps), 128 q-rows (16/warp), kv tile 64 as 2x32 halves.
// q pre-scaled by 0.125 and tf32-rounded; K/V double-buffered via cp.async.
// __launch_bounds__(256,2): cap regs at 128 -> 2 CTAs/SM = 16 warps/SM.
#define KSTR 68
#define VSTR 72
#define PSTR 68

__device__ __forceinline__ void flash_issue(unsigned* sK, unsigned* sV,
                                            const float* kb, const float* vb, int tid) {
#pragma unroll
    for (int p = 0; p < 4; p++) {
        int idx = tid + p * 256;        // 0..1023
        int r = idx >> 4, c4 = (idx & 15) * 4;
        cpa16(sptr(&sK[r * KSTR + c4]), kb + (size_t)r * DIM + c4);
        cpa16(sptr(&sV[r * VSTR + c4]), vb + (size_t)r * DIM + c4);
    }
}

__global__ __launch_bounds__(256, 2) void flash_tf32_kernel(const float* __restrict__ q,
                                                            const float* __restrict__ k,
                                                            const float* __restrict__ v,
                                                            float* __restrict__ o) {
    extern __shared__ unsigned sm[];
    unsigned* sKB[2] = {sm, sm + 64 * KSTR};
    unsigned* sVB[2] = {sm + 2 * 64 * KSTR, sm + 2 * 64 * KSTR + 64 * VSTR};
    unsigned* sP = sm + 2 * 64 * KSTR + 2 * 64 * VSTR;   // 128*PSTR (Q staging at init)

    int tid = threadIdx.x;
    int lane = tid & 31, wid = tid >> 5;
    int g = lane >> 2, t4 = lane & 3;
    int b = blockIdx.z, h = blockIdx.y;
    int m0 = blockIdx.x * 128;
    int qr = wid * 16;                   // warp owns 16 q-rows

    const float* kb0 = k + ((size_t)(b * SEQ)) * DIM + h * DK;
    const float* vb0 = v + ((size_t)(b * SEQ)) * DIM + h * DK;
    const float* qbase = q + ((size_t)(b * SEQ + m0)) * DIM + h * DK;

    // group 0: Q tile (128x64 floats = 2048 x 16B chunks) staged into sP via cp.async
#pragma unroll
    for (int p = 0; p < 8; p++) {
        int idx = tid + p * 256;        // 0..2047
        int r = idx >> 4, c4 = (idx & 15) * 4;
        cpa16(sptr(&sP[r * PSTR + c4]), qbase + (size_t)r * DIM + c4);
    }
    cpa_commit();
    // group 1: KV tile 0
    flash_issue(sKB[0], sVB[0], kb0, vb0, tid);
    cpa_commit();

    cpa_wait<1>();   // Q (group 0) complete; KV0 may still be in flight
    __syncthreads();
    unsigned qa[8][4];
#pragma unroll
    for (int kk = 0; kk < 8; kk++) {
        int base = (qr + g) * PSTR + kk * 8 + t4;
        qa[kk][0] = sP[base];
        qa[kk][1] = sP[base + 8 * PSTR];
        qa[kk][2] = sP[base + 4];
        qa[kk][3] = sP[base + 8 * PSTR + 4];
    }

    float o_[8][4] = {};
    float mlo = -1e30f, mhi = -1e30f, llo = 0.f, lhi = 0.f;

    const int NT = SEQ / 64;   // 32
    for (int i = 0; i < NT; i++) {
        int buf = i & 1;
        __syncthreads();   // all warps done reading previous buffer
        if (i + 1 < NT) {
            flash_issue(sKB[buf ^ 1], sVB[buf ^ 1],
                        kb0 + (size_t)(i + 1) * 64 * DIM,
                        vb0 + (size_t)(i + 1) * 64 * DIM, tid);
            cpa_commit();
            cpa_wait<1>();
        } else {
            cpa_wait<0>();
        }
        __syncthreads();
        unsigned* sK = sKB[buf];
        unsigned* sV = sVB[buf];

#pragma unroll
        for (int hf = 0; hf < 2; hf++) {
            // ---- S half = Q @ K[hf*32 .. hf*32+32]^T : 16x32 per warp ----
            float s[4][4] = {};
#pragma unroll
            for (int kk = 0; kk < 8; kk++) {
                unsigned bK[4][2];
#pragma unroll
                for (int ni = 0; ni < 4; ni++) {
                    int off = (hf * 32 + ni * 8 + g) * KSTR + kk * 8 + t4;
                    bK[ni][0] = sK[off];
                    bK[ni][1] = sK[off + 4];
                }
#pragma unroll
                for (int ni = 0; ni < 4; ni++)
                    mma8(s[ni], qa[kk], bK[ni]);
            }

            // ---- online softmax (q already carries 1/8 scale) ----
            {
                float rml = -1e30f, rmh = -1e30f;
#pragma unroll
                for (int ni = 0; ni < 4; ni++) {
                    rml = fmaxf(rml, fmaxf(s[ni][0], s[ni][1]));
                    rmh = fmaxf(rmh, fmaxf(s[ni][2], s[ni][3]));
                }
#pragma unroll
                for (int off = 1; off <= 2; off <<= 1) {
                    rml = fmaxf(rml, __shfl_xor_sync(0xffffffffu, rml, off));
                    rmh = fmaxf(rmh, __shfl_xor_sync(0xffffffffu, rmh, off));
                }
                float mnl = fmaxf(mlo, rml), mnh = fmaxf(mhi, rmh);
                float allo = __expf(mlo - mnl), alhi = __expf(mhi - mnh);
                float psl = 0.f, psh = 0.f;
#pragma unroll
                for (int ni = 0; ni < 4; ni++) {
                    s[ni][0] = __expf(s[ni][0] - mnl);
                    s[ni][1] = __expf(s[ni][1] - mnl);
                    s[ni][2] = __expf(s[ni][2] - mnh);
                    s[ni][3] = __expf(s[ni][3] - mnh);
                    psl += s[ni][0] + s[ni][1];
                    psh += s[ni][2] + s[ni][3];
                }
#pragma unroll
                for (int off = 1; off <= 2; off <<= 1) {
                    psl += __shfl_xor_sync(0xffffffffu, psl, off);
                    psh += __shfl_xor_sync(0xffffffffu, psh, off);
                }
                llo = llo * allo + psl;
                lhi = lhi * alhi + psh;
                mlo = mnl; mhi = mnh;
#pragma unroll
                for (int ni = 0; ni < 8; ni++) {
                    o_[ni][0] *= allo; o_[ni][1] *= allo;
                    o_[ni][2] *= alhi; o_[ni][3] *= alhi;
                }
#pragma unroll
                for (int ni = 0; ni < 4; ni++) {
                    int base = (qr + g) * PSTR + ni * 8 + 2 * t4;
                    sP[base]                = f2tf(s[ni][0]);
                    sP[base + 1]            = f2tf(s[ni][1]);
                    sP[base + 8 * PSTR]     = f2tf(s[ni][2]);
                    sP[base + 8 * PSTR + 1] = f2tf(s[ni][3]);
                }
            }
            __syncwarp();

            // ---- O += P(16x32) @ V[hf*32.., 0..64] ----
#pragma unroll
            for (int kk = 0; kk < 4; kk++) {
                unsigned pa[4];
                int base = (qr + g) * PSTR + kk * 8 + t4;
                pa[0] = sP[base];
                pa[1] = sP[base + 8 * PSTR];
                pa[2] = sP[base + 4];
                pa[3] = sP[base + 8 * PSTR + 4];
                unsigned bV[8][2];
#pragma unroll
                for (int ni = 0; ni < 8; ni++) {
                    int off = (hf * 32 + kk * 8 + t4) * VSTR + ni * 8 + g;
                    bV[ni][0] = sV[off];
                    bV[ni][1] = sV[off + 4 * VSTR];
                }
#pragma unroll
                for (int ni = 0; ni < 8; ni++)
                    mma8(o_[ni], pa, bV[ni]);
            }
            __syncwarp();   // sP rows reused by next half
        }
    }

    // ---- epilogue: tf32-round for the O-projection consumer ----
    {
        float ilo = 1.f / llo, ihi = 1.f / lhi;
        float* ob = o + ((size_t)(b * SEQ + m0 + qr + g)) * DIM + h * DK;
#pragma unroll
        for (int ni = 0; ni < 8; ni++) {
            int col = ni * 8 + 2 * t4;
            float2 r0; r0.x = f2tff(o_[ni][0] * ilo); r0.y = f2tff(o_[ni][1] * ilo);
            float2 r1; r1.x = f2tff(o_[ni][2] * ihi); r1.y = f2tff(o_[ni][3] * ihi);
            *(float2*)(ob + col) = r0;
            *(float2*)(ob + 8 * DIM + col) = r1;
        }
    }
}

#define FLASH_SMEM ((2*64*KSTR + 2*64*VSTR + 128*PSTR) * (int)sizeof(unsigned))  // 106496 B

// ---------------- launch ----------------
extern "C" void kernel_launch(void* const* d_in, const int* in_sizes, int n_in,
                              void* d_out, int out_size) {
    (void)in_sizes; (void)n_in; (void)out_size;
    const float* x     = (const float*)d_in[0];
    const float* gamma = (const float*)d_in[1];
    const float* beta  = (const float*)d_in[2];
    const float* Wq    = (const float*)d_in[3];
    const float* bq    = (const float*)d_in[4];
    const float* Wk    = (const float*)d_in[5];
    const float* bk    = (const float*)d_in[6];
    const float* Wv    = (const float*)d_in[7];
    const float* bv    = (const float*)d_in[8];
    const float* Wo    = (const float*)d_in[9];
    const float* bo    = (const float*)d_in[10];
    float* out = (float*)d_out;

    void *p_xn, *p_q, *p_k, *p_v, *p_ao, *p_wr;
    cudaGetSymbolAddress(&p_xn, g_xn);
    cudaGetSymbolAddress(&p_q,  g_q);
    cudaGetSymbolAddress(&p_k,  g_k);
    cudaGetSymbolAddress(&p_v,  g_v);
    cudaGetSymbolAddress(&p_ao, g_ao);
    cudaGetSymbolAddress(&p_wr, g_wr);
    float* xn = (float*)p_xn;
    float* qb = (float*)p_q;
    float* kb = (float*)p_k;
    float* vb = (float*)p_v;
    float* ao = (float*)p_ao;
    float* wr = (float*)p_wr;

    cudaFuncSetAttribute(flash_tf32_kernel,
                         cudaFuncAttributeMaxDynamicSharedMemorySize, FLASH_SMEM);
    cudaFuncSetAttribute(gemm_qkv_kernel,
                         cudaFuncAttributeMaxDynamicSharedMemorySize, GEMM_SMEM);
    cudaFuncSetAttribute(gemm_tf32_kernel,
                         cudaFuncAttributeMaxDynamicSharedMemorySize, GEMM_SMEM);

    ln_kernel<<<ROWS, 128>>>(x, gamma, beta, xn);

    dim3 wgrid(DIM * DIM / (256 * 4), 4);   // (256, 4)
    round_w_kernel<<<wgrid, 256>>>(Wq, Wk, Wv, Wo, wr);

    dim3 qkvgrid(DIM / 128, ROWS / 128, 3);   // (4, 64, 3)
    gemm_qkv_kernel<<<qkvgrid, 128, GEMM_SMEM>>>(xn, wr, bq, qb, bk, kb, bv, vb);

    dim3 fgrid(SEQ / 128, HEADS, BATCH);  // (16, 8, 4)
    flash_tf32_kernel<<<fgrid, 256, FLASH_SMEM>>>(qb, kb, vb, ao);

    dim3 ggrid(DIM / 128, ROWS / 128);   // (4, 64)
    gemm_tf32_kernel<<<ggrid, 128, GEMM_SMEM>>>(ao, wr + 3 * DIM * DIM, bo, out);
}

// round 14
// speedup vs baseline: 1.8711x; 1.8711x over previous
#include <cuda_runtime.h>
#include <cuda_fp16.h>
#include <math.h>

#define BATCH 4
#define SEQ   2048
#define DIM   512
#define HEADS 8
#define DK    64
#define ROWS  (BATCH*SEQ)   // 8192

// ---------------- scratch (static device arrays; no allocation) ----------------
__device__ __half g_xn[ROWS*DIM];
__device__ __half g_q [ROWS*DIM];
__device__ __half g_k [ROWS*DIM];
__device__ __half g_v [ROWS*DIM];
__device__ __half g_vt[ROWS*DIM];          // V transposed: [b][h][d][seq]
__device__ __half g_ao[ROWS*DIM];
__device__ __half g_wh[4*DIM*DIM];         // fp16 weights: Wq,Wk,Wv,Wo

// ---------------- helpers ----------------
__device__ __forceinline__ unsigned pack_h2(float lo, float hi) {
    __half2 h = __floats2half2_rn(lo, hi);   // .x = lo (low half), .y = hi
    return *(unsigned*)&h;
}
__device__ __forceinline__ void mma16(float* c, const unsigned* a, const unsigned* b) {
    asm volatile("mma.sync.aligned.m16n8k16.row.col.f32.f16.f16.f32 "
        "{%0,%1,%2,%3}, {%4,%5,%6,%7}, {%8,%9}, {%0,%1,%2,%3};"
        : "+f"(c[0]), "+f"(c[1]), "+f"(c[2]), "+f"(c[3])
        : "r"(a[0]), "r"(a[1]), "r"(a[2]), "r"(a[3]), "r"(b[0]), "r"(b[1]));
}
__device__ __forceinline__ unsigned sptr(const void* p) {
    return (unsigned)__cvta_generic_to_shared(p);
}
__device__ __forceinline__ void cpa16(unsigned dst, const void* src) {
    asm volatile("cp.async.cg.shared.global [%0], [%1], 16;" :: "r"(dst), "l"(src));
}
__device__ __forceinline__ void cpa_commit() { asm volatile("cp.async.commit_group;"); }
template<int N> __device__ __forceinline__ void cpa_wait() {
    asm volatile("cp.async.wait_group %0;" :: "n"(N));
}

// ---------------- LayerNorm: one block per row (fp16 output) ----------------
__global__ void ln_kernel(const float* __restrict__ x,
                          const float* __restrict__ gamma,
                          const float* __restrict__ beta,
                          __half* __restrict__ out) {
    int row = blockIdx.x;
    const float* xr = x + (size_t)row * DIM;
    int t = threadIdx.x;
    float vals[4];
    float s = 0.f, ss = 0.f;
#pragma unroll
    for (int i = 0; i < 4; i++) {
        float v = xr[t + i * 128];
        vals[i] = v; s += v; ss += v * v;
    }
#pragma unroll
    for (int off = 16; off; off >>= 1) {
        s  += __shfl_xor_sync(0xffffffffu, s,  off);
        ss += __shfl_xor_sync(0xffffffffu, ss, off);
    }
    __shared__ float red0[4], red1[4];
    int w = t >> 5;
    if ((t & 31) == 0) { red0[w] = s; red1[w] = ss; }
    __syncthreads();
    s  = red0[0] + red0[1] + red0[2] + red0[3];
    ss = red1[0] + red1[1] + red1[2] + red1[3];
    float mu   = s * (1.0f / DIM);
    float var  = ss * (1.0f / DIM) - mu * mu;
    float rstd = rsqrtf(var + 1e-5f);
    __half* outr = out + (size_t)row * DIM;
#pragma unroll
    for (int i = 0; i < 4; i++) {
        int c = t + i * 128;
        outr[c] = __float2half_rn((vals[i] - mu) * rstd * gamma[c] + beta[c]);
    }
}

// ---------------- weight fp16 conversion (4MB read -> 2MB write) ----------------
__global__ void round_w_kernel(const float* __restrict__ Wq, const float* __restrict__ Wk,
                               const float* __restrict__ Wv, const float* __restrict__ Wo,
                               __half* __restrict__ out) {
    const float* src = (blockIdx.y == 0) ? Wq : (blockIdx.y == 1) ? Wk
                     : (blockIdx.y == 2) ? Wv : Wo;
    int i = (blockIdx.x * 256 + threadIdx.x) * 4;
    float4 v = *(const float4*)(src + i);
    unsigned* dst = (unsigned*)(out + (size_t)blockIdx.y * DIM * DIM + i);
    dst[0] = pack_h2(v.x, v.y);
    dst[1] = pack_h2(v.z, v.w);
}

// ---------------- V transpose: [token][dim] -> [b][h][d][seq] ----------------
__global__ void vtrans_kernel(const __half* __restrict__ v, __half* __restrict__ vt) {
    __shared__ __half s[64][65];
    int t0 = blockIdx.x * 64;
    int h  = blockIdx.y;
    int b  = blockIdx.z;
    int tid = threadIdx.x;
    const __half* src = v + ((size_t)(b * SEQ + t0)) * DIM + h * DK;
#pragma unroll
    for (int p = 0; p < 8; p++) {
        int lin = tid + p * 256;        // 0..2047 words (64 rows x 32 words)
        int r = lin >> 5, w = lin & 31;
        unsigned u = *(const unsigned*)(src + (size_t)r * DIM + 2 * w);
        __half2 hh = *(__half2*)&u;
        s[r][2 * w]     = hh.x;
        s[r][2 * w + 1] = hh.y;
    }
    __syncthreads();
    __half* dst = vt + ((size_t)((b * HEADS + h) * DK)) * SEQ + t0;
#pragma unroll
    for (int p = 0; p < 8; p++) {
        int lin = tid + p * 256;        // 0..2047: d = lin>>5, w = lin&31
        int d = lin >> 5, w = lin & 31;
        __half2 hh;
        hh.x = s[2 * w][d];
        hh.y = s[2 * w + 1][d];
        *(unsigned*)(dst + (size_t)d * SEQ + 2 * w) = *(unsigned*)&hh;
    }
}

// ---------------- FP16 tensor-core GEMM (cp.async double-buffered) ----------------
// Y[M,512] = (A[M,512] @ W[512,512]^T + bias) * scale. A, W fp16; acc fp32.
// Block tile 128x128, BK=32 halfs (16 words), 128 threads (4 warps, warp tile 64x64).
#define GSTR 20   // smem row stride in 32-bit words

__device__ __forceinline__ void gemm_issue(unsigned* As, unsigned* Bs,
                                           const __half* Abase, const __half* Wbase,
                                           int k0, int tid) {
#pragma unroll
    for (int p = 0; p < 4; p++) {
        int idx = tid + p * 128;
        int r = idx >> 2, c = idx & 3;          // 4 x 16B chunks per row (64B)
        cpa16(sptr(&As[r * GSTR + c * 4]), Abase + (size_t)r * 512 + k0 + c * 8);
        cpa16(sptr(&Bs[r * GSTR + c * 4]), Wbase + (size_t)r * 512 + k0 + c * 8);
    }
}

__device__ __forceinline__ void gemm_fp16_body(const __half* __restrict__ A,
                                               const __half* __restrict__ W,
                                               const float* __restrict__ bias,
                                               void* __restrict__ Y,
                                               unsigned* sm, bool half_out,
                                               float out_scale) {
    unsigned* AsB[2] = {sm,              sm + 128 * GSTR};
    unsigned* BsB[2] = {sm + 2*128*GSTR, sm + 3*128*GSTR};
    int tid = threadIdx.x;
    int lane = tid & 31, wid = tid >> 5;
    int g = lane >> 2, t4 = lane & 3;
    int wm = (wid & 1) * 64;
    int wn = (wid >> 1) * 64;
    int m0 = blockIdx.y * 128, n0 = blockIdx.x * 128;

    float c[4][8][4] = {};

    const __half* Abase = A + (size_t)m0 * 512;
    const __half* Wbase = W + (size_t)n0 * 512;

    gemm_issue(AsB[0], BsB[0], Abase, Wbase, 0, tid);  cpa_commit();
    gemm_issue(AsB[1], BsB[1], Abase, Wbase, 32, tid); cpa_commit();

    int buf = 0;
    for (int it = 0; it < 16; it++) {       // 16 chunks of 32 halfs
        if (it == 15) cpa_wait<0>(); else cpa_wait<1>();
        __syncthreads();
        unsigned* As = AsB[buf];
        unsigned* Bs = BsB[buf];
#pragma unroll
        for (int ks = 0; ks < 2; ks++) {    // 2 x k16 per chunk
            int kw = ks * 8;
            unsigned a[4][4], b[8][2];
#pragma unroll
            for (int mi = 0; mi < 4; mi++) {
                int base = (wm + mi * 16 + g) * GSTR + kw + t4;
                a[mi][0] = As[base];
                a[mi][1] = As[base + 8 * GSTR];
                a[mi][2] = As[base + 4];
                a[mi][3] = As[base + 8 * GSTR + 4];
            }
#pragma unroll
            for (int ni = 0; ni < 8; ni++) {
                int bb = (wn + ni * 8 + g) * GSTR + kw + t4;
                b[ni][0] = Bs[bb];
                b[ni][1] = Bs[bb + 4];
            }
#pragma unroll
            for (int mi = 0; mi < 4; mi++)
#pragma unroll
                for (int ni = 0; ni < 8; ni++)
                    mma16(c[mi][ni], a[mi], b[ni]);
        }
        __syncthreads();
        if (it < 14) {
            gemm_issue(As, Bs, Abase, Wbase, (it + 2) * 32, tid);
            cpa_commit();
        }
        buf ^= 1;
    }

#pragma unroll
    for (int mi = 0; mi < 4; mi++) {
        int row = m0 + wm + mi * 16 + g;
#pragma unroll
        for (int ni = 0; ni < 8; ni++) {
            int col = n0 + wn + ni * 8 + 2 * t4;
            float2 bv = *(const float2*)(bias + col);
            if (half_out) {
                __half* Yh = (__half*)Y;
                *(unsigned*)(Yh + (size_t)row * 512 + col) =
                    pack_h2((c[mi][ni][0] + bv.x) * out_scale,
                            (c[mi][ni][1] + bv.y) * out_scale);
                *(unsigned*)(Yh + (size_t)(row + 8) * 512 + col) =
                    pack_h2((c[mi][ni][2] + bv.x) * out_scale,
                            (c[mi][ni][3] + bv.y) * out_scale);
            } else {
                float* Yf = (float*)Y;
                float2 o0; o0.x = c[mi][ni][0] + bv.x; o0.y = c[mi][ni][1] + bv.y;
                float2 o1; o1.x = c[mi][ni][2] + bv.x; o1.y = c[mi][ni][3] + bv.y;
                *(float2*)(Yf + (size_t)row * 512 + col) = o0;
                *(float2*)(Yf + (size_t)(row + 8) * 512 + col) = o1;
            }
        }
    }
}

#define GEMM_SMEM (4 * 128 * GSTR * (int)sizeof(unsigned))   // 40960 B

__global__ __launch_bounds__(128) void gemm_qkv_kernel(const __half* __restrict__ A,
                                                       const __half* __restrict__ Wh,
                                                       const float* __restrict__ bq,
                                                       __half* __restrict__ Yq,
                                                       const float* __restrict__ bk,
                                                       __half* __restrict__ Yk,
                                                       const float* __restrict__ bv,
                                                       __half* __restrict__ Yv) {
    extern __shared__ unsigned gsm[];
    const float* bias; __half* Y; float scl;
    if (blockIdx.z == 0)      { bias = bq; Y = Yq; scl = 0.125f; }   // fold DK^-0.5
    else if (blockIdx.z == 1) { bias = bk; Y = Yk; scl = 1.0f; }
    else                      { bias = bv; Y = Yv; scl = 1.0f; }
    const __half* W = Wh + (size_t)blockIdx.z * DIM * DIM;
    gemm_fp16_body(A, W, bias, Y, gsm, true, scl);
}

__global__ __launch_bounds__(128) void gemm_o_kernel(const __half* __restrict__ A,
                                                     const __half* __restrict__ W,
                                                     const float* __restrict__ bias,
                                                     float* __restrict__ Y) {
    extern __shared__ unsigned gsm[];
    gemm_fp16_body(A, W, bias, Y, gsm, false, 1.0f);
}

// ---------------- FP16 tensor-core flash attention ----------------
// Block: 128 thr (4 warps), 128 q-rows (32/warp), kv tile 64 as 2x32 halves.
// q pre-scaled; K [kv][d], V^T [d][kv] in smem; all fp16, fp32 softmax/accum.
#define KSTR 36
#define VSTR 36
#define PSTR 36

__device__ __forceinline__ void flash_issue(unsigned* sK, unsigned* sV,
                                            const __half* kb, const __half* vtb,
                                            int kt, int tid) {
#pragma unroll
    for (int p = 0; p < 4; p++) {
        int idx = tid + p * 128;        // 0..511: r = row, c = 16B chunk (8 halfs)
        int r = idx >> 3, c = idx & 7;
        cpa16(sptr(&sK[r * KSTR + c * 4]), kb + (size_t)(kt + r) * DIM + c * 8);
        cpa16(sptr(&sV[r * VSTR + c * 4]), vtb + (size_t)r * SEQ + kt + c * 8);
    }
}

__global__ __launch_bounds__(128) void flash_fp16_kernel(const __half* __restrict__ q,
                                                         const __half* __restrict__ k,
                                                         const __half* __restrict__ vt,
                                                         __half* __restrict__ o) {
    extern __shared__ unsigned sm[];
    unsigned* sKB[2] = {sm, sm + 64 * KSTR};
    unsigned* sVB[2] = {sm + 2 * 64 * KSTR, sm + 2 * 64 * KSTR + 64 * VSTR};
    unsigned* sP = sm + 2 * 64 * KSTR + 2 * 64 * VSTR;   // 128*PSTR (Q staging at init)

    int tid = threadIdx.x;
    int lane = tid & 31, wid = tid >> 5;
    int g = lane >> 2, t4 = lane & 3;
    int b = blockIdx.z, h = blockIdx.y;
    int m0 = blockIdx.x * 128;
    int qr = wid * 32;

    const __half* kb   = k  + ((size_t)(b * SEQ)) * DIM + h * DK;
    const __half* vtb  = vt + ((size_t)((b * HEADS + h) * DK)) * SEQ;
    const __half* qbase = q + ((size_t)(b * SEQ + m0)) * DIM + h * DK;

    // group 0: Q tile (128 rows x 64 halfs = 128B/row = 8 chunks) into sP
#pragma unroll
    for (int p = 0; p < 8; p++) {
        int idx = tid + p * 128;        // 0..1023
        int r = idx >> 3, c = idx & 7;
        cpa16(sptr(&sP[r * PSTR + c * 4]), qbase + (size_t)r * DIM + c * 8);
    }
    cpa_commit();
    // group 1: KV tile 0
    flash_issue(sKB[0], sVB[0], kb, vtb, 0, tid);
    cpa_commit();

    cpa_wait<1>();   // Q complete; KV0 may still be in flight
    __syncthreads();
    unsigned qa[2][4][4];
#pragma unroll
    for (int mi = 0; mi < 2; mi++)
#pragma unroll
    for (int kk = 0; kk < 4; kk++) {
        int base = (qr + mi * 16 + g) * PSTR + kk * 8 + t4;
        qa[mi][kk][0] = sP[base];
        qa[mi][kk][1] = sP[base + 8 * PSTR];
        qa[mi][kk][2] = sP[base + 4];
        qa[mi][kk][3] = sP[base + 8 * PSTR + 4];
    }

    float o_[2][8][4] = {};
    float ml[2][2], ll[2][2];
#pragma unroll
    for (int mi = 0; mi < 2; mi++) { ml[mi][0] = ml[mi][1] = -1e30f; ll[mi][0] = ll[mi][1] = 0.f; }

    const int NT = SEQ / 64;   // 32
    for (int i = 0; i < NT; i++) {
        int buf = i & 1;
        __syncthreads();
        if (i + 1 < NT) {
            flash_issue(sKB[buf ^ 1], sVB[buf ^ 1], kb, vtb, (i + 1) * 64, tid);
            cpa_commit();
            cpa_wait<1>();
        } else {
            cpa_wait<0>();
        }
        __syncthreads();
        unsigned* sK = sKB[buf];
        unsigned* sV = sVB[buf];

#pragma unroll
        for (int hf = 0; hf < 2; hf++) {
            // ---- S half = Q @ K[hf*32..+32]^T : 32x32 per warp, k=64 d (4 x k16) ----
            float s[2][4][4] = {};
#pragma unroll
            for (int kk = 0; kk < 4; kk++) {
                unsigned bK[4][2];
#pragma unroll
                for (int ni = 0; ni < 4; ni++) {
                    int off = (hf * 32 + ni * 8 + g) * KSTR + kk * 8 + t4;
                    bK[ni][0] = sK[off];
                    bK[ni][1] = sK[off + 4];
                }
#pragma unroll
                for (int mi = 0; mi < 2; mi++)
#pragma unroll
                    for (int ni = 0; ni < 4; ni++)
                        mma16(s[mi][ni], qa[mi][kk], bK[ni]);
            }

            // ---- online softmax (q already carries 1/8 scale) ----
#pragma unroll
            for (int mi = 0; mi < 2; mi++) {
                float rml = -1e30f, rmh = -1e30f;
#pragma unroll
                for (int ni = 0; ni < 4; ni++) {
                    rml = fmaxf(rml, fmaxf(s[mi][ni][0], s[mi][ni][1]));
                    rmh = fmaxf(rmh, fmaxf(s[mi][ni][2], s[mi][ni][3]));
                }
#pragma unroll
                for (int off = 1; off <= 2; off <<= 1) {
                    rml = fmaxf(rml, __shfl_xor_sync(0xffffffffu, rml, off));
                    rmh = fmaxf(rmh, __shfl_xor_sync(0xffffffffu, rmh, off));
                }
                float mnl = fmaxf(ml[mi][0], rml), mnh = fmaxf(ml[mi][1], rmh);
                float allo = __expf(ml[mi][0] - mnl), alhi = __expf(ml[mi][1] - mnh);
                float psl = 0.f, psh = 0.f;
#pragma unroll
                for (int ni = 0; ni < 4; ni++) {
                    s[mi][ni][0] = __expf(s[mi][ni][0] - mnl);
                    s[mi][ni][1] = __expf(s[mi][ni][1] - mnl);
                    s[mi][ni][2] = __expf(s[mi][ni][2] - mnh);
                    s[mi][ni][3] = __expf(s[mi][ni][3] - mnh);
                    psl += s[mi][ni][0] + s[mi][ni][1];
                    psh += s[mi][ni][2] + s[mi][ni][3];
                }
#pragma unroll
                for (int off = 1; off <= 2; off <<= 1) {
                    psl += __shfl_xor_sync(0xffffffffu, psl, off);
                    psh += __shfl_xor_sync(0xffffffffu, psh, off);
                }
                ll[mi][0] = ll[mi][0] * allo + psl;
                ll[mi][1] = ll[mi][1] * alhi + psh;
                ml[mi][0] = mnl; ml[mi][1] = mnh;
#pragma unroll
                for (int ni = 0; ni < 8; ni++) {
                    o_[mi][ni][0] *= allo; o_[mi][ni][1] *= allo;
                    o_[mi][ni][2] *= alhi; o_[mi][ni][3] *= alhi;
                }
                // store P (fp16 pairs) into warp-private sP rows, kv words 0..15
#pragma unroll
                for (int ni = 0; ni < 4; ni++) {
                    int base = (qr + mi * 16 + g) * PSTR + ni * 4 + t4;
                    sP[base]            = pack_h2(s[mi][ni][0], s[mi][ni][1]);
                    sP[base + 8 * PSTR] = pack_h2(s[mi][ni][2], s[mi][ni][3]);
                }
            }
            __syncwarp();

            // ---- O += P(32x32) @ V^T[., hf*32..+32] : k = 32 kv (2 x k16) ----
#pragma unroll
            for (int kk = 0; kk < 2; kk++) {
                unsigned pa[2][4];
#pragma unroll
                for (int mi = 0; mi < 2; mi++) {
                    int base = (qr + mi * 16 + g) * PSTR + kk * 8 + t4;
                    pa[mi][0] = sP[base];
                    pa[mi][1] = sP[base + 8 * PSTR];
                    pa[mi][2] = sP[base + 4];
                    pa[mi][3] = sP[base + 8 * PSTR + 4];
                }
                unsigned bV[8][2];
#pragma unroll
                for (int ni = 0; ni < 8; ni++) {
                    int off = (ni * 8 + g) * VSTR + hf * 16 + kk * 8 + t4;
                    bV[ni][0] = sV[off];
                    bV[ni][1] = sV[off + 4];
                }
#pragma unroll
                for (int mi = 0; mi < 2; mi++)
#pragma unroll
                    for (int ni = 0; ni < 8; ni++)
                        mma16(o_[mi][ni], pa[mi], bV[ni]);
            }
            __syncwarp();   // sP rows reused by next half
        }
    }

    // ---- epilogue: fp16 output for the O-projection consumer ----
#pragma unroll
    for (int mi = 0; mi < 2; mi++) {
        float ilo = 1.f / ll[mi][0], ihi = 1.f / ll[mi][1];
        __half* ob = o + ((size_t)(b * SEQ + m0 + qr + mi * 16 + g)) * DIM + h * DK;
#pragma unroll
        for (int ni = 0; ni < 8; ni++) {
            int col = ni * 8 + 2 * t4;
            *(unsigned*)(ob + col) =
                pack_h2(o_[mi][ni][0] * ilo, o_[mi][ni][1] * ilo);
            *(unsigned*)(ob + 8 * DIM + col) =
                pack_h2(o_[mi][ni][2] * ihi, o_[mi][ni][3] * ihi);
        }
    }
}

#define FLASH_SMEM ((2*64*KSTR + 2*64*VSTR + 128*PSTR) * (int)sizeof(unsigned))  // 55296 B

// ---------------- launch ----------------
extern "C" void kernel_launch(void* const* d_in, const int* in_sizes, int n_in,
                              void* d_out, int out_size) {
    (void)in_sizes; (void)n_in; (void)out_size;
    const float* x     = (const float*)d_in[0];
    const float* gamma = (const float*)d_in[1];
    const float* beta  = (const float*)d_in[2];
    const float* Wq    = (const float*)d_in[3];
    const float* bq    = (const float*)d_in[4];
    const float* Wk    = (const float*)d_in[5];
    const float* bk    = (const float*)d_in[6];
    const float* Wv    = (const float*)d_in[7];
    const float* bv    = (const float*)d_in[8];
    const float* Wo    = (const float*)d_in[9];
    const float* bo    = (const float*)d_in[10];
    float* out = (float*)d_out;

    void *p_xn, *p_q, *p_k, *p_v, *p_vt, *p_ao, *p_wh;
    cudaGetSymbolAddress(&p_xn, g_xn);
    cudaGetSymbolAddress(&p_q,  g_q);
    cudaGetSymbolAddress(&p_k,  g_k);
    cudaGetSymbolAddress(&p_v,  g_v);
    cudaGetSymbolAddress(&p_vt, g_vt);
    cudaGetSymbolAddress(&p_ao, g_ao);
    cudaGetSymbolAddress(&p_wh, g_wh);
    __half* xn  = (__half*)p_xn;
    __half* qb  = (__half*)p_q;
    __half* kbf = (__half*)p_k;
    __half* vb  = (__half*)p_v;
    __half* vtb = (__half*)p_vt;
    __half* ao  = (__half*)p_ao;
    __half* wh  = (__half*)p_wh;

    cudaFuncSetAttribute(flash_fp16_kernel,
                         cudaFuncAttributeMaxDynamicSharedMemorySize, FLASH_SMEM);
    cudaFuncSetAttribute(gemm_qkv_kernel,
                         cudaFuncAttributeMaxDynamicSharedMemorySize, GEMM_SMEM);
    cudaFuncSetAttribute(gemm_o_kernel,
                         cudaFuncAttributeMaxDynamicSharedMemorySize, GEMM_SMEM);

    ln_kernel<<<ROWS, 128>>>(x, gamma, beta, xn);

    dim3 wgrid(DIM * DIM / (256 * 4), 4);   // (256, 4)
    round_w_kernel<<<wgrid, 256>>>(Wq, Wk, Wv, Wo, wh);

    dim3 qkvgrid(DIM / 128, ROWS / 128, 3);   // (4, 64, 3)
    gemm_qkv_kernel<<<qkvgrid, 128, GEMM_SMEM>>>(xn, wh, bq, qb, bk, kbf, bv, vb);

    dim3 tgrid(SEQ / 64, HEADS, BATCH);   // (32, 8, 4)
    vtrans_kernel<<<tgrid, 256>>>(vb, vtb);

    dim3 fgrid(SEQ / 128, HEADS, BATCH);  // (16, 8, 4)
    flash_fp16_kernel<<<fgrid, 128, FLASH_SMEM>>>(qb, kbf, vtb, ao);

    dim3 ggrid(DIM / 128, ROWS / 128);   // (4, 64)
    gemm_o_kernel<<<ggrid, 128, GEMM_SMEM>>>(ao, wh + (size_t)3 * DIM * DIM, bo, out);
}

// round 15
// speedup vs baseline: 1.9138x; 1.0228x over previous
#include <cuda_runtime.h>
#include <cuda_fp16.h>
#include <math.h>

#define BATCH 4
#define SEQ   2048
#define DIM   512
#define HEADS 8
#define DK    64
#define ROWS  (BATCH*SEQ)   // 8192

// ---------------- scratch (static device arrays; no allocation) ----------------
__device__ __half g_xn[ROWS*DIM];
__device__ __half g_q [ROWS*DIM];
__device__ __half g_k [ROWS*DIM];
__device__ __half g_v [ROWS*DIM];
__device__ __half g_vt[ROWS*DIM];          // V transposed: [b][h][d][seq]
__device__ __half g_ao[ROWS*DIM];
__device__ __half g_wh[4*DIM*DIM];         // fp16 weights: Wq,Wk,Wv,Wo

// ---------------- helpers ----------------
__device__ __forceinline__ unsigned pack_h2(float lo, float hi) {
    __half2 h = __floats2half2_rn(lo, hi);   // .x = lo (low half), .y = hi
    return *(unsigned*)&h;
}
__device__ __forceinline__ void mma16(float* c, const unsigned* a, const unsigned* b) {
    asm volatile("mma.sync.aligned.m16n8k16.row.col.f32.f16.f16.f32 "
        "{%0,%1,%2,%3}, {%4,%5,%6,%7}, {%8,%9}, {%0,%1,%2,%3};"
        : "+f"(c[0]), "+f"(c[1]), "+f"(c[2]), "+f"(c[3])
        : "r"(a[0]), "r"(a[1]), "r"(a[2]), "r"(a[3]), "r"(b[0]), "r"(b[1]));
}
__device__ __forceinline__ unsigned sptr(const void* p) {
    return (unsigned)__cvta_generic_to_shared(p);
}
__device__ __forceinline__ void cpa16(unsigned dst, const void* src) {
    asm volatile("cp.async.cg.shared.global [%0], [%1], 16;" :: "r"(dst), "l"(src));
}
__device__ __forceinline__ void cpa_commit() { asm volatile("cp.async.commit_group;"); }
template<int N> __device__ __forceinline__ void cpa_wait() {
    asm volatile("cp.async.wait_group %0;" :: "n"(N));
}

// ---------------- LayerNorm: one block per row (fp16 output) ----------------
__global__ void ln_kernel(const float* __restrict__ x,
                          const float* __restrict__ gamma,
                          const float* __restrict__ beta,
                          __half* __restrict__ out) {
    int row = blockIdx.x;
    const float* xr = x + (size_t)row * DIM;
    int t = threadIdx.x;
    float vals[4];
    float s = 0.f, ss = 0.f;
#pragma unroll
    for (int i = 0; i < 4; i++) {
        float v = xr[t + i * 128];
        vals[i] = v; s += v; ss += v * v;
    }
#pragma unroll
    for (int off = 16; off; off >>= 1) {
        s  += __shfl_xor_sync(0xffffffffu, s,  off);
        ss += __shfl_xor_sync(0xffffffffu, ss, off);
    }
    __shared__ float red0[4], red1[4];
    int w = t >> 5;
    if ((t & 31) == 0) { red0[w] = s; red1[w] = ss; }
    __syncthreads();
    s  = red0[0] + red0[1] + red0[2] + red0[3];
    ss = red1[0] + red1[1] + red1[2] + red1[3];
    float mu   = s * (1.0f / DIM);
    float var  = ss * (1.0f / DIM) - mu * mu;
    float rstd = rsqrtf(var + 1e-5f);
    __half* outr = out + (size_t)row * DIM;
#pragma unroll
    for (int i = 0; i < 4; i++) {
        int c = t + i * 128;
        outr[c] = __float2half_rn((vals[i] - mu) * rstd * gamma[c] + beta[c]);
    }
}

// ---------------- weight fp16 conversion (4MB read -> 2MB write) ----------------
__global__ void round_w_kernel(const float* __restrict__ Wq, const float* __restrict__ Wk,
                               const float* __restrict__ Wv, const float* __restrict__ Wo,
                               __half* __restrict__ out) {
    const float* src = (blockIdx.y == 0) ? Wq : (blockIdx.y == 1) ? Wk
                     : (blockIdx.y == 2) ? Wv : Wo;
    int i = (blockIdx.x * 256 + threadIdx.x) * 4;
    float4 v = *(const float4*)(src + i);
    unsigned* dst = (unsigned*)(out + (size_t)blockIdx.y * DIM * DIM + i);
    dst[0] = pack_h2(v.x, v.y);
    dst[1] = pack_h2(v.z, v.w);
}

// ---------------- V transpose: [token][dim] -> [b][h][d][seq] ----------------
__global__ void vtrans_kernel(const __half* __restrict__ v, __half* __restrict__ vt) {
    __shared__ __half s[64][65];
    int t0 = blockIdx.x * 64;
    int h  = blockIdx.y;
    int b  = blockIdx.z;
    int tid = threadIdx.x;
    const __half* src = v + ((size_t)(b * SEQ + t0)) * DIM + h * DK;
#pragma unroll
    for (int p = 0; p < 8; p++) {
        int lin = tid + p * 256;        // 0..2047 words (64 rows x 32 words)
        int r = lin >> 5, w = lin & 31;
        unsigned u = *(const unsigned*)(src + (size_t)r * DIM + 2 * w);
        __half2 hh = *(__half2*)&u;
        s[r][2 * w]     = hh.x;
        s[r][2 * w + 1] = hh.y;
    }
    __syncthreads();
    __half* dst = vt + ((size_t)((b * HEADS + h) * DK)) * SEQ + t0;
#pragma unroll
    for (int p = 0; p < 8; p++) {
        int lin = tid + p * 256;        // 0..2047: d = lin>>5, w = lin&31
        int d = lin >> 5, w = lin & 31;
        __half2 hh;
        hh.x = s[2 * w][d];
        hh.y = s[2 * w + 1][d];
        *(unsigned*)(dst + (size_t)d * SEQ + 2 * w) = *(unsigned*)&hh;
    }
}

// ---------------- FP16 tensor-core GEMM (cp.async double-buffered) ----------------
// Y[M,512] = (A[M,512] @ W[512,512]^T + bias) * scale. A, W fp16; acc fp32.
// Block tile 128x128, BK=32 halfs (16 words), 128 threads (4 warps, warp tile 64x64).
#define GSTR 20   // smem row stride in 32-bit words

__device__ __forceinline__ void gemm_issue(unsigned* As, unsigned* Bs,
                                           const __half* Abase, const __half* Wbase,
                                           int k0, int tid) {
#pragma unroll
    for (int p = 0; p < 4; p++) {
        int idx = tid + p * 128;
        int r = idx >> 2, c = idx & 3;          // 4 x 16B chunks per row (64B)
        cpa16(sptr(&As[r * GSTR + c * 4]), Abase + (size_t)r * 512 + k0 + c * 8);
        cpa16(sptr(&Bs[r * GSTR + c * 4]), Wbase + (size_t)r * 512 + k0 + c * 8);
    }
}

__device__ __forceinline__ void gemm_fp16_body(const __half* __restrict__ A,
                                               const __half* __restrict__ W,
                                               const float* __restrict__ bias,
                                               void* __restrict__ Y,
                                               unsigned* sm, bool half_out,
                                               float out_scale) {
    unsigned* AsB[2] = {sm,              sm + 128 * GSTR};
    unsigned* BsB[2] = {sm + 2*128*GSTR, sm + 3*128*GSTR};
    int tid = threadIdx.x;
    int lane = tid & 31, wid = tid >> 5;
    int g = lane >> 2, t4 = lane & 3;
    int wm = (wid & 1) * 64;
    int wn = (wid >> 1) * 64;
    int m0 = blockIdx.y * 128, n0 = blockIdx.x * 128;

    float c[4][8][4] = {};

    const __half* Abase = A + (size_t)m0 * 512;
    const __half* Wbase = W + (size_t)n0 * 512;

    gemm_issue(AsB[0], BsB[0], Abase, Wbase, 0, tid);  cpa_commit();
    gemm_issue(AsB[1], BsB[1], Abase, Wbase, 32, tid); cpa_commit();

    int buf = 0;
    for (int it = 0; it < 16; it++) {       // 16 chunks of 32 halfs
        if (it == 15) cpa_wait<0>(); else cpa_wait<1>();
        __syncthreads();
        unsigned* As = AsB[buf];
        unsigned* Bs = BsB[buf];
#pragma unroll
        for (int ks = 0; ks < 2; ks++) {    // 2 x k16 per chunk
            int kw = ks * 8;
            unsigned a[4][4], b[8][2];
#pragma unroll
            for (int mi = 0; mi < 4; mi++) {
                int base = (wm + mi * 16 + g) * GSTR + kw + t4;
                a[mi][0] = As[base];
                a[mi][1] = As[base + 8 * GSTR];
                a[mi][2] = As[base + 4];
                a[mi][3] = As[base + 8 * GSTR + 4];
            }
#pragma unroll
            for (int ni = 0; ni < 8; ni++) {
                int bb = (wn + ni * 8 + g) * GSTR + kw + t4;
                b[ni][0] = Bs[bb];
                b[ni][1] = Bs[bb + 4];
            }
#pragma unroll
            for (int mi = 0; mi < 4; mi++)
#pragma unroll
                for (int ni = 0; ni < 8; ni++)
                    mma16(c[mi][ni], a[mi], b[ni]);
        }
        __syncthreads();
        if (it < 14) {
            gemm_issue(As, Bs, Abase, Wbase, (it + 2) * 32, tid);
            cpa_commit();
        }
        buf ^= 1;
    }

#pragma unroll
    for (int mi = 0; mi < 4; mi++) {
        int row = m0 + wm + mi * 16 + g;
#pragma unroll
        for (int ni = 0; ni < 8; ni++) {
            int col = n0 + wn + ni * 8 + 2 * t4;
            float2 bv = *(const float2*)(bias + col);
            if (half_out) {
                __half* Yh = (__half*)Y;
                *(unsigned*)(Yh + (size_t)row * 512 + col) =
                    pack_h2((c[mi][ni][0] + bv.x) * out_scale,
                            (c[mi][ni][1] + bv.y) * out_scale);
                *(unsigned*)(Yh + (size_t)(row + 8) * 512 + col) =
                    pack_h2((c[mi][ni][2] + bv.x) * out_scale,
                            (c[mi][ni][3] + bv.y) * out_scale);
            } else {
                float* Yf = (float*)Y;
                float2 o0; o0.x = c[mi][ni][0] + bv.x; o0.y = c[mi][ni][1] + bv.y;
                float2 o1; o1.x = c[mi][ni][2] + bv.x; o1.y = c[mi][ni][3] + bv.y;
                *(float2*)(Yf + (size_t)row * 512 + col) = o0;
                *(float2*)(Yf + (size_t)(row + 8) * 512 + col) = o1;
            }
        }
    }
}

#define GEMM_SMEM (4 * 128 * GSTR * (int)sizeof(unsigned))   // 40960 B

__global__ __launch_bounds__(128) void gemm_qkv_kernel(const __half* __restrict__ A,
                                                       const __half* __restrict__ Wh,
                                                       const float* __restrict__ bq,
                                                       __half* __restrict__ Yq,
                                                       const float* __restrict__ bk,
                                                       __half* __restrict__ Yk,
                                                       const float* __restrict__ bv,
                                                       __half* __restrict__ Yv) {
    extern __shared__ unsigned gsm[];
    const float* bias; __half* Y; float scl;
    if (blockIdx.z == 0)      { bias = bq; Y = Yq; scl = 0.125f; }   // fold DK^-0.5
    else if (blockIdx.z == 1) { bias = bk; Y = Yk; scl = 1.0f; }
    else                      { bias = bv; Y = Yv; scl = 1.0f; }
    const __half* W = Wh + (size_t)blockIdx.z * DIM * DIM;
    gemm_fp16_body(A, W, bias, Y, gsm, true, scl);
}

__global__ __launch_bounds__(128) void gemm_o_kernel(const __half* __restrict__ A,
                                                     const __half* __restrict__ W,
                                                     const float* __restrict__ bias,
                                                     float* __restrict__ Y) {
    extern __shared__ unsigned gsm[];
    gemm_fp16_body(A, W, bias, Y, gsm, false, 1.0f);
}

// ---------------- FP16 tensor-core flash attention ----------------
// Block: 128 thr (4 warps), 128 q-rows (32/warp), kv tile 64 as 2x32 halves.
// P stays in REGISTERS (fp16 C-fragment == A-fragment layout): no smem round trip.
#define KSTR 36
#define VSTR 36
#define PSTR 36

__device__ __forceinline__ void flash_issue(unsigned* sK, unsigned* sV,
                                            const __half* kb, const __half* vtb,
                                            int kt, int tid) {
#pragma unroll
    for (int p = 0; p < 4; p++) {
        int idx = tid + p * 128;        // 0..511: r = row, c = 16B chunk (8 halfs)
        int r = idx >> 3, c = idx & 7;
        cpa16(sptr(&sK[r * KSTR + c * 4]), kb + (size_t)(kt + r) * DIM + c * 8);
        cpa16(sptr(&sV[r * VSTR + c * 4]), vtb + (size_t)r * SEQ + kt + c * 8);
    }
}

__global__ __launch_bounds__(128) void flash_fp16_kernel(const __half* __restrict__ q,
                                                         const __half* __restrict__ k,
                                                         const __half* __restrict__ vt,
                                                         __half* __restrict__ o) {
    extern __shared__ unsigned sm[];
    unsigned* sKB[2] = {sm, sm + 64 * KSTR};
    unsigned* sVB[2] = {sm + 2 * 64 * KSTR, sm + 2 * 64 * KSTR + 64 * VSTR};
    unsigned* sP = sm + 2 * 64 * KSTR + 2 * 64 * VSTR;   // Q staging only

    int tid = threadIdx.x;
    int lane = tid & 31, wid = tid >> 5;
    int g = lane >> 2, t4 = lane & 3;
    int b = blockIdx.z, h = blockIdx.y;
    int m0 = blockIdx.x * 128;
    int qr = wid * 32;

    const __half* kb   = k  + ((size_t)(b * SEQ)) * DIM + h * DK;
    const __half* vtb  = vt + ((size_t)((b * HEADS + h) * DK)) * SEQ;
    const __half* qbase = q + ((size_t)(b * SEQ + m0)) * DIM + h * DK;

    // group 0: Q tile (128 rows x 64 halfs = 128B/row = 8 chunks) into sP
#pragma unroll
    for (int p = 0; p < 8; p++) {
        int idx = tid + p * 128;        // 0..1023
        int r = idx >> 3, c = idx & 7;
        cpa16(sptr(&sP[r * PSTR + c * 4]), qbase + (size_t)r * DIM + c * 8);
    }
    cpa_commit();
    // group 1: KV tile 0
    flash_issue(sKB[0], sVB[0], kb, vtb, 0, tid);
    cpa_commit();

    cpa_wait<1>();   // Q complete; KV0 may still be in flight
    __syncthreads();
    unsigned qa[2][4][4];
#pragma unroll
    for (int mi = 0; mi < 2; mi++)
#pragma unroll
    for (int kk = 0; kk < 4; kk++) {
        int base = (qr + mi * 16 + g) * PSTR + kk * 8 + t4;
        qa[mi][kk][0] = sP[base];
        qa[mi][kk][1] = sP[base + 8 * PSTR];
        qa[mi][kk][2] = sP[base + 4];
        qa[mi][kk][3] = sP[base + 8 * PSTR + 4];
    }

    float o_[2][8][4] = {};
    float ml[2][2], ll[2][2];
#pragma unroll
    for (int mi = 0; mi < 2; mi++) { ml[mi][0] = ml[mi][1] = -1e30f; ll[mi][0] = ll[mi][1] = 0.f; }

    const int NT = SEQ / 64;   // 32
    for (int i = 0; i < NT; i++) {
        int buf = i & 1;
        __syncthreads();
        if (i + 1 < NT) {
            flash_issue(sKB[buf ^ 1], sVB[buf ^ 1], kb, vtb, (i + 1) * 64, tid);
            cpa_commit();
            cpa_wait<1>();
        } else {
            cpa_wait<0>();
        }
        __syncthreads();
        unsigned* sK = sKB[buf];
        unsigned* sV = sVB[buf];

#pragma unroll
        for (int hf = 0; hf < 2; hf++) {
            // ---- S half = Q @ K[hf*32..+32]^T : 32x32 per warp, k=64 d (4 x k16) ----
            float s[2][4][4] = {};
#pragma unroll
            for (int kk = 0; kk < 4; kk++) {
                unsigned bK[4][2];
#pragma unroll
                for (int ni = 0; ni < 4; ni++) {
                    int off = (hf * 32 + ni * 8 + g) * KSTR + kk * 8 + t4;
                    bK[ni][0] = sK[off];
                    bK[ni][1] = sK[off + 4];
                }
#pragma unroll
                for (int mi = 0; mi < 2; mi++)
#pragma unroll
                    for (int ni = 0; ni < 4; ni++)
                        mma16(s[mi][ni], qa[mi][kk], bK[ni]);
            }

            // ---- online softmax; exp(S) stays in s[][] (fp32) ----
#pragma unroll
            for (int mi = 0; mi < 2; mi++) {
                float rml = -1e30f, rmh = -1e30f;
#pragma unroll
                for (int ni = 0; ni < 4; ni++) {
                    rml = fmaxf(rml, fmaxf(s[mi][ni][0], s[mi][ni][1]));
                    rmh = fmaxf(rmh, fmaxf(s[mi][ni][2], s[mi][ni][3]));
                }
#pragma unroll
                for (int off = 1; off <= 2; off <<= 1) {
                    rml = fmaxf(rml, __shfl_xor_sync(0xffffffffu, rml, off));
                    rmh = fmaxf(rmh, __shfl_xor_sync(0xffffffffu, rmh, off));
                }
                float mnl = fmaxf(ml[mi][0], rml), mnh = fmaxf(ml[mi][1], rmh);
                float allo = __expf(ml[mi][0] - mnl), alhi = __expf(ml[mi][1] - mnh);
                float psl = 0.f, psh = 0.f;
#pragma unroll
                for (int ni = 0; ni < 4; ni++) {
                    s[mi][ni][0] = __expf(s[mi][ni][0] - mnl);
                    s[mi][ni][1] = __expf(s[mi][ni][1] - mnl);
                    s[mi][ni][2] = __expf(s[mi][ni][2] - mnh);
                    s[mi][ni][3] = __expf(s[mi][ni][3] - mnh);
                    psl += s[mi][ni][0] + s[mi][ni][1];
                    psh += s[mi][ni][2] + s[mi][ni][3];
                }
#pragma unroll
                for (int off = 1; off <= 2; off <<= 1) {
                    psl += __shfl_xor_sync(0xffffffffu, psl, off);
                    psh += __shfl_xor_sync(0xffffffffu, psh, off);
                }
                ll[mi][0] = ll[mi][0] * allo + psl;
                ll[mi][1] = ll[mi][1] * alhi + psh;
                ml[mi][0] = mnl; ml[mi][1] = mnh;
#pragma unroll
                for (int ni = 0; ni < 8; ni++) {
                    o_[mi][ni][0] *= allo; o_[mi][ni][1] *= allo;
                    o_[mi][ni][2] *= alhi; o_[mi][ni][3] *= alhi;
                }
            }

            // ---- O += P(32x32) @ V^T : P packed from S fragments IN REGISTERS ----
            // C-fragment (row g, col 2t4) == A-fragment (row g, k 2t4) for fp16:
            // pa[0] = s[2kk][0..1], pa[1] = s[2kk][2..3] (row+8),
            // pa[2] = s[2kk+1][0..1] (k+8), pa[3] = s[2kk+1][2..3].
#pragma unroll
            for (int kk = 0; kk < 2; kk++) {
                unsigned pa[2][4];
#pragma unroll
                for (int mi = 0; mi < 2; mi++) {
                    pa[mi][0] = pack_h2(s[mi][2 * kk][0],     s[mi][2 * kk][1]);
                    pa[mi][1] = pack_h2(s[mi][2 * kk][2],     s[mi][2 * kk][3]);
                    pa[mi][2] = pack_h2(s[mi][2 * kk + 1][0], s[mi][2 * kk + 1][1]);
                    pa[mi][3] = pack_h2(s[mi][2 * kk + 1][2], s[mi][2 * kk + 1][3]);
                }
                unsigned bV[8][2];
#pragma unroll
                for (int ni = 0; ni < 8; ni++) {
                    int off = (ni * 8 + g) * VSTR + hf * 16 + kk * 8 + t4;
                    bV[ni][0] = sV[off];
                    bV[ni][1] = sV[off + 4];
                }
#pragma unroll
                for (int mi = 0; mi < 2; mi++)
#pragma unroll
                    for (int ni = 0; ni < 8; ni++)
                        mma16(o_[mi][ni], pa[mi], bV[ni]);
            }
        }
    }

    // ---- epilogue: fp16 output for the O-projection consumer ----
#pragma unroll
    for (int mi = 0; mi < 2; mi++) {
        float ilo = 1.f / ll[mi][0], ihi = 1.f / ll[mi][1];
        __half* ob = o + ((size_t)(b * SEQ + m0 + qr + mi * 16 + g)) * DIM + h * DK;
#pragma unroll
        for (int ni = 0; ni < 8; ni++) {
            int col = ni * 8 + 2 * t4;
            *(unsigned*)(ob + col) =
                pack_h2(o_[mi][ni][0] * ilo, o_[mi][ni][1] * ilo);
            *(unsigned*)(ob + 8 * DIM + col) =
                pack_h2(o_[mi][ni][2] * ihi, o_[mi][ni][3] * ihi);
        }
    }
}

#define FLASH_SMEM ((2*64*KSTR + 2*64*VSTR + 128*PSTR) * (int)sizeof(unsigned))  // 55296 B

// ---------------- launch ----------------
extern "C" void kernel_launch(void* const* d_in, const int* in_sizes, int n_in,
                              void* d_out, int out_size) {
    (void)in_sizes; (void)n_in; (void)out_size;
    const float* x     = (const float*)d_in[0];
    const float* gamma = (const float*)d_in[1];
    const float* beta  = (const float*)d_in[2];
    const float* Wq    = (const float*)d_in[3];
    const float* bq    = (const float*)d_in[4];
    const float* Wk    = (const float*)d_in[5];
    const float* bk    = (const float*)d_in[6];
    const float* Wv    = (const float*)d_in[7];
    const float* bv    = (const float*)d_in[8];
    const float* Wo    = (const float*)d_in[9];
    const float* bo    = (const float*)d_in[10];
    float* out = (float*)d_out;

    void *p_xn, *p_q, *p_k, *p_v, *p_vt, *p_ao, *p_wh;
    cudaGetSymbolAddress(&p_xn, g_xn);
    cudaGetSymbolAddress(&p_q,  g_q);
    cudaGetSymbolAddress(&p_k,  g_k);
    cudaGetSymbolAddress(&p_v,  g_v);
    cudaGetSymbolAddress(&p_vt, g_vt);
    cudaGetSymbolAddress(&p_ao, g_ao);
    cudaGetSymbolAddress(&p_wh, g_wh);
    __half* xn  = (__half*)p_xn;
    __half* qb  = (__half*)p_q;
    __half* kbf = (__half*)p_k;
    __half* vb  = (__half*)p_v;
    __half* vtb = (__half*)p_vt;
    __half* ao  = (__half*)p_ao;
    __half* wh  = (__half*)p_wh;

    cudaFuncSetAttribute(flash_fp16_kernel,
                         cudaFuncAttributeMaxDynamicSharedMemorySize, FLASH_SMEM);
    cudaFuncSetAttribute(gemm_qkv_kernel,
                         cudaFuncAttributeMaxDynamicSharedMemorySize, GEMM_SMEM);
    cudaFuncSetAttribute(gemm_o_kernel,
                         cudaFuncAttributeMaxDynamicSharedMemorySize, GEMM_SMEM);

    ln_kernel<<<ROWS, 128>>>(x, gamma, beta, xn);

    dim3 wgrid(DIM * DIM / (256 * 4), 4);   // (256, 4)
    round_w_kernel<<<wgrid, 256>>>(Wq, Wk, Wv, Wo, wh);

    dim3 qkvgrid(DIM / 128, ROWS / 128, 3);   // (4, 64, 3)
    gemm_qkv_kernel<<<qkvgrid, 128, GEMM_SMEM>>>(xn, wh, bq, qb, bk, kbf, bv, vb);

    dim3 tgrid(SEQ / 64, HEADS, BATCH);   // (32, 8, 4)
    vtrans_kernel<<<tgrid, 256>>>(vb, vtb);

    dim3 fgrid(SEQ / 128, HEADS, BATCH);  // (16, 8, 4)
    flash_fp16_kernel<<<fgrid, 128, FLASH_SMEM>>>(qb, kbf, vtb, ao);

    dim3 ggrid(DIM / 128, ROWS / 128);   // (4, 64)
    gemm_o_kernel<<<ggrid, 128, GEMM_SMEM>>>(ao, wh + (size_t)3 * DIM * DIM, bo, out);
}

// round 16
// speedup vs baseline: 2.1654x; 1.1315x over previous
#include <cuda_runtime.h>
#include <cuda_fp16.h>
#include <math.h>

#define BATCH 4
#define SEQ   2048
#define DIM   512
#define HEADS 8
#define DK    64
#define ROWS  (BATCH*SEQ)   // 8192

// ---------------- scratch (static device arrays; no allocation) ----------------
__device__ __half g_xn[ROWS*DIM];
__device__ __half g_q [ROWS*DIM];
__device__ __half g_k [ROWS*DIM];
__device__ __half g_v [ROWS*DIM];
__device__ __half g_vt[ROWS*DIM];          // V transposed: [b][h][d][seq]
__device__ __half g_ao[ROWS*DIM];
__device__ __half g_wh[4*DIM*DIM];         // fp16 weights: Wq,Wk,Wv,Wo

// ---------------- helpers ----------------
__device__ __forceinline__ unsigned pack_h2(float lo, float hi) {
    __half2 h = __floats2half2_rn(lo, hi);
    return *(unsigned*)&h;
}
__device__ __forceinline__ void mma16(float* c, const unsigned* a, const unsigned* b) {
    asm volatile("mma.sync.aligned.m16n8k16.row.col.f32.f16.f16.f32 "
        "{%0,%1,%2,%3}, {%4,%5,%6,%7}, {%8,%9}, {%0,%1,%2,%3};"
        : "+f"(c[0]), "+f"(c[1]), "+f"(c[2]), "+f"(c[3])
        : "r"(a[0]), "r"(a[1]), "r"(a[2]), "r"(a[3]), "r"(b[0]), "r"(b[1]));
}
#define LDSM4(r0, r1, r2, r3, addr) \
    asm volatile("ldmatrix.sync.aligned.m8n8.x4.shared.b16 {%0,%1,%2,%3}, [%4];" \
        : "=r"(r0), "=r"(r1), "=r"(r2), "=r"(r3) : "r"(addr))
__device__ __forceinline__ unsigned sptr(const void* p) {
    return (unsigned)__cvta_generic_to_shared(p);
}
__device__ __forceinline__ void cpa16(unsigned dst, const void* src) {
    asm volatile("cp.async.cg.shared.global [%0], [%1], 16;" :: "r"(dst), "l"(src));
}
__device__ __forceinline__ void cpa_commit() { asm volatile("cp.async.commit_group;"); }
template<int N> __device__ __forceinline__ void cpa_wait() {
    asm volatile("cp.async.wait_group %0;" :: "n"(N));
}

// ---------------- LayerNorm: one block per row (fp16 output) ----------------
__global__ void ln_kernel(const float* __restrict__ x,
                          const float* __restrict__ gamma,
                          const float* __restrict__ beta,
                          __half* __restrict__ out) {
    int row = blockIdx.x;
    const float* xr = x + (size_t)row * DIM;
    int t = threadIdx.x;
    float vals[4];
    float s = 0.f, ss = 0.f;
#pragma unroll
    for (int i = 0; i < 4; i++) {
        float v = xr[t + i * 128];
        vals[i] = v; s += v; ss += v * v;
    }
#pragma unroll
    for (int off = 16; off; off >>= 1) {
        s  += __shfl_xor_sync(0xffffffffu, s,  off);
        ss += __shfl_xor_sync(0xffffffffu, ss, off);
    }
    __shared__ float red0[4], red1[4];
    int w = t >> 5;
    if ((t & 31) == 0) { red0[w] = s; red1[w] = ss; }
    __syncthreads();
    s  = red0[0] + red0[1] + red0[2] + red0[3];
    ss = red1[0] + red1[1] + red1[2] + red1[3];
    float mu   = s * (1.0f / DIM);
    float var  = ss * (1.0f / DIM) - mu * mu;
    float rstd = rsqrtf(var + 1e-5f);
    __half* outr = out + (size_t)row * DIM;
#pragma unroll
    for (int i = 0; i < 4; i++) {
        int c = t + i * 128;
        outr[c] = __float2half_rn((vals[i] - mu) * rstd * gamma[c] + beta[c]);
    }
}

// ---------------- weight fp16 conversion ----------------
__global__ void round_w_kernel(const float* __restrict__ Wq, const float* __restrict__ Wk,
                               const float* __restrict__ Wv, const float* __restrict__ Wo,
                               __half* __restrict__ out) {
    const float* src = (blockIdx.y == 0) ? Wq : (blockIdx.y == 1) ? Wk
                     : (blockIdx.y == 2) ? Wv : Wo;
    int i = (blockIdx.x * 256 + threadIdx.x) * 4;
    float4 v = *(const float4*)(src + i);
    unsigned* dst = (unsigned*)(out + (size_t)blockIdx.y * DIM * DIM + i);
    dst[0] = pack_h2(v.x, v.y);
    dst[1] = pack_h2(v.z, v.w);
}

// ---------------- V transpose: [token][dim] -> [b][h][d][seq] ----------------
__global__ void vtrans_kernel(const __half* __restrict__ v, __half* __restrict__ vt) {
    __shared__ __half s[64][65];
    int t0 = blockIdx.x * 64;
    int h  = blockIdx.y;
    int b  = blockIdx.z;
    int tid = threadIdx.x;
    const __half* src = v + ((size_t)(b * SEQ + t0)) * DIM + h * DK;
#pragma unroll
    for (int p = 0; p < 8; p++) {
        int lin = tid + p * 256;
        int r = lin >> 5, w = lin & 31;
        unsigned u = *(const unsigned*)(src + (size_t)r * DIM + 2 * w);
        __half2 hh = *(__half2*)&u;
        s[r][2 * w]     = hh.x;
        s[r][2 * w + 1] = hh.y;
    }
    __syncthreads();
    __half* dst = vt + ((size_t)((b * HEADS + h) * DK)) * SEQ + t0;
#pragma unroll
    for (int p = 0; p < 8; p++) {
        int lin = tid + p * 256;
        int d = lin >> 5, w = lin & 31;
        __half2 hh;
        hh.x = s[2 * w][d];
        hh.y = s[2 * w + 1][d];
        *(unsigned*)(dst + (size_t)d * SEQ + 2 * w) = *(unsigned*)&hh;
    }
}

// ---------------- FP16 tensor-core GEMM (cp.async + ldmatrix) ----------------
// Block tile 128x128, BK=32 halfs, 128 threads (4 warps, warp tile 64x64).
#define GSTR 20   // smem row stride in 32-bit words (ldmatrix conflict-free)

__device__ __forceinline__ void gemm_issue(unsigned* As, unsigned* Bs,
                                           const __half* Abase, const __half* Wbase,
                                           int k0, int tid) {
#pragma unroll
    for (int p = 0; p < 4; p++) {
        int idx = tid + p * 128;
        int r = idx >> 2, c = idx & 3;
        cpa16(sptr(&As[r * GSTR + c * 4]), Abase + (size_t)r * 512 + k0 + c * 8);
        cpa16(sptr(&Bs[r * GSTR + c * 4]), Wbase + (size_t)r * 512 + k0 + c * 8);
    }
}

__device__ __forceinline__ void gemm_fp16_body(const __half* __restrict__ A,
                                               const __half* __restrict__ W,
                                               const float* __restrict__ bias,
                                               void* __restrict__ Y,
                                               unsigned* sm, bool half_out,
                                               float out_scale) {
    unsigned* AsB[2] = {sm,              sm + 128 * GSTR};
    unsigned* BsB[2] = {sm + 2*128*GSTR, sm + 3*128*GSTR};
    int tid = threadIdx.x;
    int lane = tid & 31, wid = tid >> 5;
    int g = lane >> 2, t4 = lane & 3;
    int wm = (wid & 1) * 64;
    int wn = (wid >> 1) * 64;
    int m0 = blockIdx.y * 128, n0 = blockIdx.x * 128;

    // ldmatrix per-lane geometry
    int rA = ((lane >> 4) << 3) | (lane & 7);   // 0..15: row within 16-row group
    int ws = ((lane >> 3) & 1) << 4;            // 0 or 16 bytes: k8-chunk select
    int r16 = lane & 15;                        // A-tile row select
    int wsA = (lane >> 4) << 4;                 // A-tile chunk select (bytes)

    float c[4][8][4] = {};

    const __half* Abase = A + (size_t)m0 * 512;
    const __half* Wbase = W + (size_t)n0 * 512;

    gemm_issue(AsB[0], BsB[0], Abase, Wbase, 0, tid);  cpa_commit();
    gemm_issue(AsB[1], BsB[1], Abase, Wbase, 32, tid); cpa_commit();

    int buf = 0;
    for (int it = 0; it < 16; it++) {
        if (it == 15) cpa_wait<0>(); else cpa_wait<1>();
        __syncthreads();
        unsigned asa = sptr(AsB[buf]);
        unsigned bsa = sptr(BsB[buf]);
#pragma unroll
        for (int ks = 0; ks < 2; ks++) {
            int kb = ks * 32;                   // k16 byte offset within row
            unsigned a[4][4], b[8][2];
#pragma unroll
            for (int mi = 0; mi < 4; mi++) {
                unsigned addr = asa + (unsigned)((wm + mi * 16 + r16) * (GSTR * 4) + kb + wsA);
                LDSM4(a[mi][0], a[mi][1], a[mi][2], a[mi][3], addr);
            }
#pragma unroll
            for (int j = 0; j < 4; j++) {
                unsigned addr = bsa + (unsigned)((wn + j * 16 + rA) * (GSTR * 4) + kb + ws);
                LDSM4(b[2*j][0], b[2*j][1], b[2*j+1][0], b[2*j+1][1], addr);
            }
#pragma unroll
            for (int mi = 0; mi < 4; mi++)
#pragma unroll
                for (int ni = 0; ni < 8; ni++)
                    mma16(c[mi][ni], a[mi], b[ni]);
        }
        __syncthreads();
        if (it < 14) {
            gemm_issue(AsB[buf], BsB[buf], Abase, Wbase, (it + 2) * 32, tid);
            cpa_commit();
        }
        buf ^= 1;
    }

#pragma unroll
    for (int mi = 0; mi < 4; mi++) {
        int row = m0 + wm + mi * 16 + g;
#pragma unroll
        for (int ni = 0; ni < 8; ni++) {
            int col = n0 + wn + ni * 8 + 2 * t4;
            float2 bv = *(const float2*)(bias + col);
            if (half_out) {
                __half* Yh = (__half*)Y;
                *(unsigned*)(Yh + (size_t)row * 512 + col) =
                    pack_h2((c[mi][ni][0] + bv.x) * out_scale,
                            (c[mi][ni][1] + bv.y) * out_scale);
                *(unsigned*)(Yh + (size_t)(row + 8) * 512 + col) =
                    pack_h2((c[mi][ni][2] + bv.x) * out_scale,
                            (c[mi][ni][3] + bv.y) * out_scale);
            } else {
                float* Yf = (float*)Y;
                float2 o0; o0.x = c[mi][ni][0] + bv.x; o0.y = c[mi][ni][1] + bv.y;
                float2 o1; o1.x = c[mi][ni][2] + bv.x; o1.y = c[mi][ni][3] + bv.y;
                *(float2*)(Yf + (size_t)row * 512 + col) = o0;
                *(float2*)(Yf + (size_t)(row + 8) * 512 + col) = o1;
            }
        }
    }
}

#define GEMM_SMEM (4 * 128 * GSTR * (int)sizeof(unsigned))   // 40960 B

__global__ __launch_bounds__(128) void gemm_qkv_kernel(const __half* __restrict__ A,
                                                       const __half* __restrict__ Wh,
                                                       const float* __restrict__ bq,
                                                       __half* __restrict__ Yq,
                                                       const float* __restrict__ bk,
                                                       __half* __restrict__ Yk,
                                                       const float* __restrict__ bv,
                                                       __half* __restrict__ Yv) {
    extern __shared__ unsigned gsm[];
    const float* bias; __half* Y; float scl;
    if (blockIdx.z == 0)      { bias = bq; Y = Yq; scl = 0.125f; }
    else if (blockIdx.z == 1) { bias = bk; Y = Yk; scl = 1.0f; }
    else                      { bias = bv; Y = Yv; scl = 1.0f; }
    const __half* W = Wh + (size_t)blockIdx.z * DIM * DIM;
    gemm_fp16_body(A, W, bias, Y, gsm, true, scl);
}

__global__ __launch_bounds__(128) void gemm_o_kernel(const __half* __restrict__ A,
                                                     const __half* __restrict__ W,
                                                     const float* __restrict__ bias,
                                                     float* __restrict__ Y) {
    extern __shared__ unsigned gsm[];
    gemm_fp16_body(A, W, bias, Y, gsm, false, 1.0f);
}

// ---------------- FP16 tensor-core flash attention (ldmatrix fragments) ----------------
// Block: 128 thr (4 warps), 128 q-rows (32/warp), kv tile 64 as 2x32 halves.
// P stays in registers (C-fragment == A-fragment layout).
#define KSTR 36
#define VSTR 36
#define PSTR 36

__device__ __forceinline__ void flash_issue(unsigned* sK, unsigned* sV,
                                            const __half* kb, const __half* vtb,
                                            int kt, int tid) {
#pragma unroll
    for (int p = 0; p < 4; p++) {
        int idx = tid + p * 128;
        int r = idx >> 3, c = idx & 7;
        cpa16(sptr(&sK[r * KSTR + c * 4]), kb + (size_t)(kt + r) * DIM + c * 8);
        cpa16(sptr(&sV[r * VSTR + c * 4]), vtb + (size_t)r * SEQ + kt + c * 8);
    }
}

__global__ __launch_bounds__(128) void flash_fp16_kernel(const __half* __restrict__ q,
                                                         const __half* __restrict__ k,
                                                         const __half* __restrict__ vt,
                                                         __half* __restrict__ o) {
    extern __shared__ unsigned sm[];
    unsigned* sKB[2] = {sm, sm + 64 * KSTR};
    unsigned* sVB[2] = {sm + 2 * 64 * KSTR, sm + 2 * 64 * KSTR + 64 * VSTR};
    unsigned* sP = sm + 2 * 64 * KSTR + 2 * 64 * VSTR;   // Q staging only

    int tid = threadIdx.x;
    int lane = tid & 31, wid = tid >> 5;
    int g = lane >> 2, t4 = lane & 3;
    int b = blockIdx.z, h = blockIdx.y;
    int m0 = blockIdx.x * 128;
    int qr = wid * 32;

    int rA = ((lane >> 4) << 3) | (lane & 7);   // ldmatrix row within 16-group
    int ws = ((lane >> 3) & 1) << 4;            // 0/16 B chunk select

    const __half* kb   = k  + ((size_t)(b * SEQ)) * DIM + h * DK;
    const __half* vtb  = vt + ((size_t)((b * HEADS + h) * DK)) * SEQ;
    const __half* qbase = q + ((size_t)(b * SEQ + m0)) * DIM + h * DK;

    // group 0: Q tile into sP
#pragma unroll
    for (int p = 0; p < 8; p++) {
        int idx = tid + p * 128;
        int r = idx >> 3, c = idx & 7;
        cpa16(sptr(&sP[r * PSTR + c * 4]), qbase + (size_t)r * DIM + c * 8);
    }
    cpa_commit();
    flash_issue(sKB[0], sVB[0], kb, vtb, 0, tid);
    cpa_commit();

    cpa_wait<1>();
    __syncthreads();
    unsigned qa[2][4][4];
#pragma unroll
    for (int mi = 0; mi < 2; mi++)
#pragma unroll
    for (int kk = 0; kk < 4; kk++) {
        int base = (qr + mi * 16 + g) * PSTR + kk * 8 + t4;
        qa[mi][kk][0] = sP[base];
        qa[mi][kk][1] = sP[base + 8 * PSTR];
        qa[mi][kk][2] = sP[base + 4];
        qa[mi][kk][3] = sP[base + 8 * PSTR + 4];
    }

    float o_[2][8][4] = {};
    float ml[2][2], ll[2][2];
#pragma unroll
    for (int mi = 0; mi < 2; mi++) { ml[mi][0] = ml[mi][1] = -1e30f; ll[mi][0] = ll[mi][1] = 0.f; }

    const int NT = SEQ / 64;   // 32
    for (int i = 0; i < NT; i++) {
        int buf = i & 1;
        __syncthreads();
        if (i + 1 < NT) {
            flash_issue(sKB[buf ^ 1], sVB[buf ^ 1], kb, vtb, (i + 1) * 64, tid);
            cpa_commit();
            cpa_wait<1>();
        } else {
            cpa_wait<0>();
        }
        __syncthreads();
        unsigned ska = sptr(sKB[buf]);
        unsigned sva = sptr(sVB[buf]);

#pragma unroll
        for (int hf = 0; hf < 2; hf++) {
            // ---- S half = Q @ K[hf*32..+32]^T ----
            float s[2][4][4] = {};
#pragma unroll
            for (int kk = 0; kk < 4; kk++) {
                unsigned bK[4][2];
                unsigned a0 = ska + (unsigned)((hf * 32 + rA) * (KSTR * 4) + kk * 32 + ws);
                LDSM4(bK[0][0], bK[0][1], bK[1][0], bK[1][1], a0);
                unsigned a1 = a0 + 16 * (KSTR * 4);
                LDSM4(bK[2][0], bK[2][1], bK[3][0], bK[3][1], a1);
#pragma unroll
                for (int mi = 0; mi < 2; mi++)
#pragma unroll
                    for (int ni = 0; ni < 4; ni++)
                        mma16(s[mi][ni], qa[mi][kk], bK[ni]);
            }

            // ---- online softmax; exp(S) stays in s[][] ----
#pragma unroll
            for (int mi = 0; mi < 2; mi++) {
                float rml = -1e30f, rmh = -1e30f;
#pragma unroll
                for (int ni = 0; ni < 4; ni++) {
                    rml = fmaxf(rml, fmaxf(s[mi][ni][0], s[mi][ni][1]));
                    rmh = fmaxf(rmh, fmaxf(s[mi][ni][2], s[mi][ni][3]));
                }
#pragma unroll
                for (int off = 1; off <= 2; off <<= 1) {
                    rml = fmaxf(rml, __shfl_xor_sync(0xffffffffu, rml, off));
                    rmh = fmaxf(rmh, __shfl_xor_sync(0xffffffffu, rmh, off));
                }
                float mnl = fmaxf(ml[mi][0], rml), mnh = fmaxf(ml[mi][1], rmh);
                float allo = __expf(ml[mi][0] - mnl), alhi = __expf(ml[mi][1] - mnh);
                float psl = 0.f, psh = 0.f;
#pragma unroll
                for (int ni = 0; ni < 4; ni++) {
                    s[mi][ni][0] = __expf(s[mi][ni][0] - mnl);
                    s[mi][ni][1] = __expf(s[mi][ni][1] - mnl);
                    s[mi][ni][2] = __expf(s[mi][ni][2] - mnh);
                    s[mi][ni][3] = __expf(s[mi][ni][3] - mnh);
                    psl += s[mi][ni][0] + s[mi][ni][1];
                    psh += s[mi][ni][2] + s[mi][ni][3];
                }
#pragma unroll
                for (int off = 1; off <= 2; off <<= 1) {
                    psl += __shfl_xor_sync(0xffffffffu, psl, off);
                    psh += __shfl_xor_sync(0xffffffffu, psh, off);
                }
                ll[mi][0] = ll[mi][0] * allo + psl;
                ll[mi][1] = ll[mi][1] * alhi + psh;
                ml[mi][0] = mnl; ml[mi][1] = mnh;
#pragma unroll
                for (int ni = 0; ni < 8; ni++) {
                    o_[mi][ni][0] *= allo; o_[mi][ni][1] *= allo;
                    o_[mi][ni][2] *= alhi; o_[mi][ni][3] *= alhi;
                }
            }

            // ---- O += P @ V^T : P from S fragments in registers ----
#pragma unroll
            for (int kk = 0; kk < 2; kk++) {
                unsigned pa[2][4];
#pragma unroll
                for (int mi = 0; mi < 2; mi++) {
                    pa[mi][0] = pack_h2(s[mi][2 * kk][0],     s[mi][2 * kk][1]);
                    pa[mi][1] = pack_h2(s[mi][2 * kk][2],     s[mi][2 * kk][3]);
                    pa[mi][2] = pack_h2(s[mi][2 * kk + 1][0], s[mi][2 * kk + 1][1]);
                    pa[mi][3] = pack_h2(s[mi][2 * kk + 1][2], s[mi][2 * kk + 1][3]);
                }
                unsigned bV[8][2];
#pragma unroll
                for (int j = 0; j < 4; j++) {
                    unsigned addr = sva + (unsigned)((j * 16 + rA) * (VSTR * 4)
                                                     + hf * 64 + kk * 32 + ws);
                    LDSM4(bV[2*j][0], bV[2*j][1], bV[2*j+1][0], bV[2*j+1][1], addr);
                }
#pragma unroll
                for (int mi = 0; mi < 2; mi++)
#pragma unroll
                    for (int ni = 0; ni < 8; ni++)
                        mma16(o_[mi][ni], pa[mi], bV[ni]);
            }
        }
    }

    // ---- epilogue ----
#pragma unroll
    for (int mi = 0; mi < 2; mi++) {
        float ilo = 1.f / ll[mi][0], ihi = 1.f / ll[mi][1];
        __half* ob = o + ((size_t)(b * SEQ + m0 + qr + mi * 16 + g)) * DIM + h * DK;
#pragma unroll
        for (int ni = 0; ni < 8; ni++) {
            int col = ni * 8 + 2 * t4;
            *(unsigned*)(ob + col) =
                pack_h2(o_[mi][ni][0] * ilo, o_[mi][ni][1] * ilo);
            *(unsigned*)(ob + 8 * DIM + col) =
                pack_h2(o_[mi][ni][2] * ihi, o_[mi][ni][3] * ihi);
        }
    }
}

#define FLASH_SMEM ((2*64*KSTR + 2*64*VSTR + 128*PSTR) * (int)sizeof(unsigned))  // 55296 B

// ---------------- launch ----------------
extern "C" void kernel_launch(void* const* d_in, const int* in_sizes, int n_in,
                              void* d_out, int out_size) {
    (void)in_sizes; (void)n_in; (void)out_size;
    const float* x     = (const float*)d_in[0];
    const float* gamma = (const float*)d_in[1];
    const float* beta  = (const float*)d_in[2];
    const float* Wq    = (const float*)d_in[3];
    const float* bq    = (const float*)d_in[4];
    const float* Wk    = (const float*)d_in[5];
    const float* bk    = (const float*)d_in[6];
    const float* Wv    = (const float*)d_in[7];
    const float* bv    = (const float*)d_in[8];
    const float* Wo    = (const float*)d_in[9];
    const float* bo    = (const float*)d_in[10];
    float* out = (float*)d_out;

    void *p_xn, *p_q, *p_k, *p_v, *p_vt, *p_ao, *p_wh;
    cudaGetSymbolAddress(&p_xn, g_xn);
    cudaGetSymbolAddress(&p_q,  g_q);
    cudaGetSymbolAddress(&p_k,  g_k);
    cudaGetSymbolAddress(&p_v,  g_v);
    cudaGetSymbolAddress(&p_vt, g_vt);
    cudaGetSymbolAddress(&p_ao, g_ao);
    cudaGetSymbolAddress(&p_wh, g_wh);
    __half* xn  = (__half*)p_xn;
    __half* qb  = (__half*)p_q;
    __half* kbf = (__half*)p_k;
    __half* vb  = (__half*)p_v;
    __half* vtb = (__half*)p_vt;
    __half* ao  = (__half*)p_ao;
    __half* wh  = (__half*)p_wh;

    cudaFuncSetAttribute(flash_fp16_kernel,
                         cudaFuncAttributeMaxDynamicSharedMemorySize, FLASH_SMEM);
    cudaFuncSetAttribute(gemm_qkv_kernel,
                         cudaFuncAttributeMaxDynamicSharedMemorySize, GEMM_SMEM);
    cudaFuncSetAttribute(gemm_o_kernel,
                         cudaFuncAttributeMaxDynamicSharedMemorySize, GEMM_SMEM);

    ln_kernel<<<ROWS, 128>>>(x, gamma, beta, xn);

    dim3 wgrid(DIM * DIM / (256 * 4), 4);   // (256, 4)
    round_w_kernel<<<wgrid, 256>>>(Wq, Wk, Wv, Wo, wh);

    dim3 qkvgrid(DIM / 128, ROWS / 128, 3);   // (4, 64, 3)
    gemm_qkv_kernel<<<qkvgrid, 128, GEMM_SMEM>>>(xn, wh, bq, qb, bk, kbf, bv, vb);

    dim3 tgrid(SEQ / 64, HEADS, BATCH);   // (32, 8, 4)
    vtrans_kernel<<<tgrid, 256>>>(vb, vtb);

    dim3 fgrid(SEQ / 128, HEADS, BATCH);  // (16, 8, 4)
    flash_fp16_kernel<<<fgrid, 128, FLASH_SMEM>>>(qb, kbf, vtb, ao);

    dim3 ggrid(DIM / 128, ROWS / 128);   // (4, 64)
    gemm_o_kernel<<<ggrid, 128, GEMM_SMEM>>>(ao, wh + (size_t)3 * DIM * DIM, bo, out);
}